// round 6
// baseline (speedup 1.0000x reference)
#include <cuda_runtime.h>

#define PI_F 3.14159265358979323846f

#define BN 32
#define NN 64
#define VOX (NN*NN*NN)      // 262144
#define NP 68               // padded plane line stride (floats): strided column passes conflict-free
#define PLANE_F (NN*NP)     // 4352 floats per plane array
#define TSTRIDE 68          // transpose scratch group stride (float2 units)

// ---------------- scratch (static device globals; no allocation allowed) ----------------
__device__ float2 g_fw[BN*VOX];          // packed spectrum Z = FFT(X_t + i*Y); reused for Z*E
__device__ float  g_mats[BN*12];         // per-batch: rm[9], c[3]

// ---------------- complex helpers ----------------
struct C2 { float re, im; };
__device__ __forceinline__ C2 cadd(C2 a, C2 b){ return C2{a.re+b.re, a.im+b.im}; }
__device__ __forceinline__ C2 csub(C2 a, C2 b){ return C2{a.re-b.re, a.im-b.im}; }
__device__ __forceinline__ C2 cmulc(C2 a, float br, float bi){ return C2{a.re*br - a.im*bi, a.re*bi + a.im*br}; }
template<int S>
__device__ __forceinline__ C2 crot(C2 x){   // multiply by (0, S)
    return (S == -1) ? C2{x.im, -x.re} : C2{-x.im, x.re};
}

// 8-point DFT, natural order in/out, sign S (-1 fwd, +1 inv)
template<int S>
__device__ __forceinline__ void fft8(C2 r[8]) {
    const float H = 0.70710678118654752440f;
    C2 a0=cadd(r[0],r[4]), a1=cadd(r[1],r[5]), a2=cadd(r[2],r[6]), a3=cadd(r[3],r[7]);
    C2 s0=csub(r[0],r[4]), s1=csub(r[1],r[5]), s2=csub(r[2],r[6]), s3=csub(r[3],r[7]);
    C2 b0=s0;
    C2 b1=cmulc(s1,  H, (float)S*H);
    C2 b2=crot<S>(s2);
    C2 b3=cmulc(s3, -H, (float)S*H);
    C2 c0=cadd(a0,a2), c1=cadd(a1,a3), d0=csub(a0,a2), d1=crot<S>(csub(a1,a3));
    C2 e0=cadd(b0,b2), e1=cadd(b1,b3), f0=csub(b0,b2), f1=crot<S>(csub(b1,b3));
    r[0]=cadd(c0,c1); r[4]=csub(c0,c1);
    r[2]=cadd(d0,d1); r[6]=csub(d0,d1);
    r[1]=cadd(e0,e1); r[5]=csub(e0,e1);
    r[3]=cadd(f0,f1); r[7]=csub(f0,f1);
}

// per-thread twiddles: tw[d-1] = exp(+i*2*pi*t*d/64), d=1..7
__device__ __forceinline__ void make_tw(C2 tw[7], int t) {
    float ang = (6.28318530717958647692f/64.f) * (float)t;
    float s, c; __sincosf(ang, &s, &c);
    tw[0] = C2{c, s};
#pragma unroll
    for (int d=1; d<7; d++)
        tw[d] = C2{tw[d-1].re*c - tw[d-1].im*s, tw[d-1].re*s + tw[d-1].im*c};
}

// Core 64-pt FFT: input r[a] = x[8a+t], output r[c] = X[8c+t].
// Tg = this group's float2 transpose scratch (>=64 cells). tw = precomputed twiddles.
template<int S>
__device__ __forceinline__ void fft64t(C2 r[8], float2* Tg, int t, const C2* tw) {
    fft8<S>(r);
#pragma unroll
    for (int d=1;d<8;d++){
        float cs = tw[d-1].re;
        float sn = (S == -1) ? -tw[d-1].im : tw[d-1].im;
        r[d] = cmulc(r[d], cs, sn);
    }
    __syncwarp();
#pragma unroll
    for (int d=0;d<8;d++){ int p = 8*d + ((d+t)&7); Tg[p] = make_float2(r[d].re, r[d].im); }
    __syncwarp();
#pragma unroll
    for (int b=0;b<8;b++){ int p = 8*t + ((b+t)&7); float2 v = Tg[p]; r[b] = C2{v.x, v.y}; }
    __syncwarp();
    fft8<S>(r);
}

// ---------------- per-batch affine parameters ----------------
__global__ void mats_kernel(const float* __restrict__ theta) {
    int b = threadIdx.x;
    if (b >= BN) return;
    float t0=theta[b*6+0], t1=theta[b*6+1], t2=theta[b*6+2];
    float t3=theta[b*6+3], t4=theta[b*6+4], t5=theta[b*6+5];
    float phi = t0*2.f*PI_F - PI_F;
    float th  = t1*2.f*PI_F - PI_F;
    float psi = t2*2.f*PI_F - PI_F;
    float cf=cosf(phi), sf=sinf(phi), ct=cosf(th), st=sinf(th), cp=cosf(psi), sp=sinf(psi);
    float r00 =  cf*ct*cp - sf*sp;
    float r01 =  sf*ct*cp + cf*sp;
    float r02 = -st*cp;
    float r10 = -cf*ct*sp - sf*cp;
    float r11 = -sf*ct*sp + cf*cp;
    float r12 =  st*sp;
    float r20 =  cf*st;
    float r21 =  sf*st;
    float r22 =  ct;
    const float s = 64.f/66.f;
    float l0 = (2.f*t3-1.f)*s, l1=(2.f*t4-1.f)*s, l2=(2.f*t5-1.f)*s;
    float* M = g_mats + b*12;
    M[0]=r00; M[1]=r01; M[2]=r02;
    M[3]=r10; M[4]=r11; M[5]=r12;
    M[6]=r20; M[7]=r21; M[8]=r22;
    M[9]  = -(r00*l0 + r01*l1 + r02*l2);
    M[10] = -(r10*l0 + r11*l1 + r12*l2);
    M[11] = -(r20*l0 + r21*l1 + r22*l2);
}

__device__ __forceinline__ void corner(float u, int hi, int& i0, int& i1, float& d) {
    float f = floorf(u);
    int ii = (int)f;
    i0 = min(max(ii, 0), hi);
    i1 = min(max(ii + 1, 0), hi);
    d = u - (float)i0;          // delta vs *clipped* lower corner (matches reference)
}

// ---------------- mask warp kernel: rotation only, 64 grid, clamp border ----------------
__global__ void warp_masks_kernel(const float* __restrict__ m1,
                                  const float* __restrict__ m2,
                                  float* __restrict__ o1, float* __restrict__ o2) {
    int idx = blockIdx.x*256 + threadIdx.x;
    int b = idx >> 18;
    int rem = idx & (VOX-1);
    int i = rem >> 12, j = (rem >> 6) & 63, k = rem & 63;
    const float* M = g_mats + b*12;
    float r00=M[0],r01=M[1],r02=M[2],r10=M[3],r11=M[4],r12=M[5],r20=M[6],r21=M[7],r22=M[8];
    int base = b << 18;

    float gx = -1.f + (float)i*(2.f/63.f);
    float gy = -1.f + (float)j*(2.f/63.f);
    float gz = -1.f + (float)k*(2.f/63.f);
    float sx = r00*gx + r01*gy + r02*gz;
    float sy = r10*gx + r11*gy + r12*gz;
    float sz = r20*gx + r21*gy + r22*gz;
    float ux = (sx+1.f)*31.5f, uy=(sy+1.f)*31.5f, uz=(sz+1.f)*31.5f;
    int x0,x1,y0,y1,z0,z1; float dx,dy,dz;
    corner(ux,63,x0,x1,dx); corner(uy,63,y0,y1,dy); corner(uz,63,z0,z1,dz);
    float wx0=1.f-dx, wy0=1.f-dy, wz0=1.f-dz;
    const float* p1 = m1 + base;
    const float* p2 = m2 + base;
    int i000=(x0<<12)+(y0<<6)+z0, i001=(x0<<12)+(y0<<6)+z1;
    int i010=(x0<<12)+(y1<<6)+z0, i011=(x0<<12)+(y1<<6)+z1;
    int i100=(x1<<12)+(y0<<6)+z0, i101=(x1<<12)+(y0<<6)+z1;
    int i110=(x1<<12)+(y1<<6)+z0, i111=(x1<<12)+(y1<<6)+z1;
    float w000=wx0*wy0*wz0, w001=wx0*wy0*dz, w010=wx0*dy*wz0, w011=wx0*dy*dz;
    float w100=dx*wy0*wz0,  w101=dx*wy0*dz,  w110=dx*dy*wz0,  w111=dx*dy*dz;
    float v1 = w000*p1[i000]+w001*p1[i001]+w010*p1[i010]+w011*p1[i011]
             + w100*p1[i100]+w101*p1[i101]+w110*p1[i110]+w111*p1[i111];
    float v2 = w000*p2[i000]+w001*p2[i001]+w010*p2[i010]+w011*p2[i011]
             + w100*p2[i100]+w101*p2[i101]+w110*p2[i110]+w111*p2[i111];
    o1[idx] = v1;
    o2[idx] = v2;
}

// ---------------- FFT kernel A: warp X inline, pack W = X_t + i*Y, forward z then y ----------------
// smem: s_re, s_im (planes) + T (float2 transpose scratch)
__global__ void __launch_bounds__(512, 2) fftA_kernel(const float* __restrict__ X,
                                                      const float* __restrict__ Y) {
    extern __shared__ float sm[];
    float* s_re = sm;
    float* s_im = sm +   PLANE_F;
    float2* T   = (float2*)(sm + 2*PLANE_F);
    int bx = blockIdx.x;                  // b*64 + x
    int b = bx >> 6, x = bx & 63;
    int tid = threadIdx.x;
    int g = tid>>3, t = tid&7;            // line y=g, octet t
    float2* Tg = T + g*TSTRIDE;

    const float* M = g_mats + b*12;
    float r00=M[0],r01=M[1],r02=M[2],r10=M[3],r11=M[4],r12=M[5],r20=M[6],r21=M[7],r22=M[8];
    float c0=M[9],c1=M[10],c2=M[11];
    const float* Xb = X + ((size_t)b << 18);
    const float* Yb = Y + ((size_t)bx << 12);   // plane (b,x) of Y, contiguous

    // padded-66 grid coords for this (x, y=g) line; z = 8a+t
    float gxc = -1.f + (float)(x+1)*(2.f/65.f);
    float gyc = -1.f + (float)(g+1)*(2.f/65.f);
    float bxs = r00*gxc + r01*gyc + c0;
    float bys = r10*gxc + r11*gyc + c1;
    float bzs = r20*gxc + r21*gyc + c2;

    C2 r[8];
#pragma unroll
    for (int a=0;a<8;a++){
        int z = 8*a + t;
        float gzc = -1.f + (float)(z+1)*(2.f/65.f);
        float sx = bxs + r02*gzc;
        float sy = bys + r12*gzc;
        float sz = bzs + r22*gzc;
        float ux=(sx+1.f)*32.5f, uy=(sy+1.f)*32.5f, uz=(sz+1.f)*32.5f;
        int x0,x1,y0,y1,z0,z1; float dx,dy,dz;
        corner(ux,65,x0,x1,dx); corner(uy,65,y0,y1,dy); corner(uz,65,z0,z1,dz);
        float wx0=1.f-dx, wy0=1.f-dy, wz0=1.f-dz;
        auto fetch = [&](int p,int q,int rr)->float{
            if ((unsigned)(p-1)<64u && (unsigned)(q-1)<64u && (unsigned)(rr-1)<64u)
                return Xb[((p-1)<<12) + ((q-1)<<6) + (rr-1)];
            return 0.f;
        };
        float v = wx0*wy0*wz0*fetch(x0,y0,z0) + wx0*wy0*dz*fetch(x0,y0,z1)
                + wx0*dy*wz0*fetch(x0,y1,z0)  + wx0*dy*dz*fetch(x0,y1,z1)
                + dx*wy0*wz0*fetch(x1,y0,z0)  + dx*wy0*dz*fetch(x1,y0,z1)
                + dx*dy*wz0*fetch(x1,y1,z0)   + dx*dy*dz*fetch(x1,y1,z1);
        float yv = Yb[(g<<6) + z];
        r[a] = C2{v, yv};                 // W = X_t + i*Y
    }

    C2 tw[7]; make_tw(tw, t);

    // forward FFT along z (in registers); store row y=g
    fft64t<-1>(r, Tg, t, tw);
#pragma unroll
    for (int c=0;c<8;c++){ int p = g*NP + (8*c+t); s_re[p]=r[c].re; s_im[p]=r[c].im; }
    __syncthreads();

    // forward FFT along y: column kz=g (conflict-free with NP=68)
#pragma unroll
    for (int a=0;a<8;a++){ int p=(8*a+t)*NP + g; r[a] = C2{s_re[p], s_im[p]}; }
    fft64t<-1>(r, Tg, t, tw);
#pragma unroll
    for (int c=0;c<8;c++){ int p=(8*c+t)*NP + g; s_re[p]=r[c].re; s_im[p]=r[c].im; }
    __syncthreads();

    float2* dst = g_fw + ((size_t)bx << 12);
#pragma unroll
    for (int i=0;i<8;i++){
        int idx = tid + i*512;
        int y = idx>>6, z = idx&63;
        dst[idx] = make_float2(s_re[y*NP+z], s_im[y*NP+z]);
    }
}

// ---------------- FFT kernel B: fwd-x, pointwise Z*E (symmetrized masks), inv-x ----------------
// E[k] = 0.5*((w1[k]+w1[-k]) - i*(w2[k]+w2[-k])), w_i[k] = M_i_t[(k+32) mod 64 per axis]
__global__ void __launch_bounds__(512, 2) fftB_kernel(const float* __restrict__ m1t,
                                                      const float* __restrict__ m2t) {
    extern __shared__ float sm[];
    float* s_re = sm;
    float* s_im = sm +   PLANE_F;
    float* e_re = sm + 2*PLANE_F;
    float* e_im = sm + 3*PLANE_F;
    float2* T   = (float2*)(sm + 4*PLANE_F);
    int bid = blockIdx.x;                 // b*64 + ky
    int b = bid >> 6, y = bid & 63;
    int tid = threadIdx.x;
    int g = tid>>3, t = tid&7;
    float2* Tg = T + g*TSTRIDE;

    size_t base = ((size_t)b << 18);
    size_t ybase = base + ((size_t)y << 6);
    int ys  = y ^ 32;
    int ys2 = (32 - y) & 63;

    // ---- phase 1: batched global loads (spectrum + masks), stage to smem ----
    {
        float2 zv[8];
#pragma unroll
        for (int i=0;i<8;i++){
            int idx = tid + i*512;
            int kx = idx>>6, kz = idx&63;
            zv[i] = g_fw[ybase + ((size_t)kx<<12) + kz];
        }
#pragma unroll
        for (int i=0;i<8;i++){
            int idx = tid + i*512;
            int kx = idx>>6, kz = idx&63;
            s_re[kx*NP+kz] = zv[i].x;
            s_im[kx*NP+kz] = zv[i].y;
        }
    }
#pragma unroll
    for (int h=0;h<2;h++){
        float a1[4], a2[4], b1[4], b2[4];
#pragma unroll
        for (int i=0;i<4;i++){
            int idx = tid + (h*4+i)*512;
            int kx = idx>>6, kz = idx&63;
            int xs  = kx ^ 32,       zs  = kz ^ 32;
            int xs2 = (32-kx) & 63,  zs2 = (32-kz) & 63;
            size_t o1 = base + ((size_t)xs <<12) + (ys <<6) + zs;
            size_t o2 = base + ((size_t)xs2<<12) + (ys2<<6) + zs2;
            a1[i] = m1t[o1]; b1[i] = m1t[o2];
            a2[i] = m2t[o1]; b2[i] = m2t[o2];
        }
#pragma unroll
        for (int i=0;i<4;i++){
            int idx = tid + (h*4+i)*512;
            int kx = idx>>6, kz = idx&63;
            e_re[kx*NP+kz] =  0.5f*(a1[i] + b1[i]);
            e_im[kx*NP+kz] = -0.5f*(a2[i] + b2[i]);
        }
    }
    __syncthreads();

    // ---- phase 2: register-resident line pipeline along x (line kz = g) ----
    C2 tw[7]; make_tw(tw, t);
    C2 r[8];
#pragma unroll
    for (int a=0;a<8;a++){
        int p = (8*a+t)*NP + g;
        r[a] = C2{s_re[p], s_im[p]};
    }
    fft64t<-1>(r, Tg, t, tw);            // forward x
#pragma unroll
    for (int c=0;c<8;c++){
        int p = (8*c+t)*NP + g;
        r[c] = cmulc(r[c], e_re[p], e_im[p]);
    }
    fft64t<1>(r, Tg, t, tw);             // inverse x
#pragma unroll
    for (int c=0;c<8;c++){
        int p = (8*c+t)*NP + g;
        s_re[p] = r[c].re; s_im[p] = r[c].im;
    }
    __syncthreads();

    // ---- phase 3: coalesced store-back ----
#pragma unroll
    for (int i=0;i<8;i++){
        int idx = tid + i*512;
        int xx = idx>>6, kz = idx&63;
        g_fw[ybase + ((size_t)xx<<12) + kz] = make_float2(s_re[xx*NP+kz], s_im[xx*NP+kz]);
    }
}

// ---------------- FFT kernel C: inverse z then y, scale, real part ----------------
__global__ void __launch_bounds__(512, 2) fftC_kernel(float* __restrict__ out0) {
    extern __shared__ float sm[];
    float* s_re = sm;
    float* s_im = sm +   PLANE_F;
    float2* T   = (float2*)(sm + 2*PLANE_F);
    int bx = blockIdx.x;
    int tid = threadIdx.x;
    int g = tid>>3, t = tid&7;
    float2* Tg = T + g*TSTRIDE;

    const float2* src = g_fw + ((size_t)bx << 12);
    C2 r[8];
#pragma unroll
    for (int a=0;a<8;a++){
        float2 v = src[(g<<6) + 8*a + t];
        r[a] = C2{v.x, v.y};
    }
    C2 tw[7]; make_tw(tw, t);
    fft64t<1>(r, Tg, t, tw);             // inverse z (line y=g)
#pragma unroll
    for (int c=0;c<8;c++){ int p = g*NP + (8*c+t); s_re[p]=r[c].re; s_im[p]=r[c].im; }
    __syncthreads();

    // inverse y: column kz=g (conflict-free with NP=68)
#pragma unroll
    for (int a=0;a<8;a++){ int p=(8*a+t)*NP + g; r[a] = C2{s_re[p], s_im[p]}; }
    fft64t<1>(r, Tg, t, tw);
#pragma unroll
    for (int c=0;c<8;c++){ int p=(8*c+t)*NP + g; s_re[p]=r[c].re; s_im[p]=r[c].im; }
    __syncthreads();

    const float sc = 1.f/262144.f;   // 1/64^3
#pragma unroll
    for (int i=0;i<8;i++){
        int idx = tid + i*512;
        int y = idx>>6, z = idx&63;
        out0[((size_t)bx<<12) + idx] = s_re[y*NP+z] * sc;
    }
}

// ---------------- launcher ----------------
extern "C" void kernel_launch(void* const* d_in, const int* in_sizes, int n_in,
                              void* d_out, int out_size) {
    const float* X  = (const float*)d_in[0];
    const float* Y  = (const float*)d_in[1];
    const float* m1 = (const float*)d_in[2];
    const float* m2 = (const float*)d_in[3];
    const float* th = (const float*)d_in[4];
    float* out0 = (float*)d_out;                 // real(ifft(...))
    float* out1 = out0 + (size_t)BN*VOX;         // M1_t
    float* out2 = out1 + (size_t)BN*VOX;         // M2_t

    const int TBYTES = NN*TSTRIDE*8;             // 34,816 B float2 scratch
    const int SMA = 2*PLANE_F*4 + TBYTES;        // 69,632 B
    const int SMB = 4*PLANE_F*4 + TBYTES;        // 104,448 B
    cudaFuncSetAttribute(fftA_kernel, cudaFuncAttributeMaxDynamicSharedMemorySize, SMA);
    cudaFuncSetAttribute(fftB_kernel, cudaFuncAttributeMaxDynamicSharedMemorySize, SMB);
    cudaFuncSetAttribute(fftC_kernel, cudaFuncAttributeMaxDynamicSharedMemorySize, SMA);

    mats_kernel<<<1, 32>>>(th);
    warp_masks_kernel<<<(BN*VOX)/256, 256>>>(m1, m2, out1, out2);
    fftA_kernel<<<BN*NN, 512, SMA>>>(X, Y);        // warp X + pack + z,y FFT -> g_fw
    fftB_kernel<<<BN*NN, 512, SMB>>>(out1, out2);  // x FFT + Z*E + x IFFT
    fftC_kernel<<<BN*NN, 512, SMA>>>(out0);        // z,y IFFT + scale + real
}

// round 7
// speedup vs baseline: 1.0299x; 1.0299x over previous
#include <cuda_runtime.h>

#define PI_F 3.14159265358979323846f

#define BN 32
#define NN 64
#define VOX (NN*NN*NN)      // 262144

// ---------------- scratch (static device globals; no allocation allowed) ----------------
__device__ float2 g_fw[BN*VOX];          // packed spectrum Z = FFT(X_t + i*Y); reused for Z*E
__device__ float  g_mats[BN*12];         // per-batch: rm[9], c[3]

// ---------------- complex helpers ----------------
struct C2 { float re, im; };
__device__ __forceinline__ C2 cadd(C2 a, C2 b){ return C2{a.re+b.re, a.im+b.im}; }
__device__ __forceinline__ C2 csub(C2 a, C2 b){ return C2{a.re-b.re, a.im-b.im}; }
__device__ __forceinline__ C2 cmulc(C2 a, float br, float bi){ return C2{a.re*br - a.im*bi, a.re*bi + a.im*br}; }
template<int S>
__device__ __forceinline__ C2 crot(C2 x){   // multiply by (0, S)
    return (S == -1) ? C2{x.im, -x.re} : C2{-x.im, x.re};
}

// 8-point DFT, natural order in/out, sign S (-1 fwd, +1 inv)
template<int S>
__device__ __forceinline__ void fft8(C2 r[8]) {
    const float H = 0.70710678118654752440f;
    C2 a0=cadd(r[0],r[4]), a1=cadd(r[1],r[5]), a2=cadd(r[2],r[6]), a3=cadd(r[3],r[7]);
    C2 s0=csub(r[0],r[4]), s1=csub(r[1],r[5]), s2=csub(r[2],r[6]), s3=csub(r[3],r[7]);
    C2 b0=s0;
    C2 b1=cmulc(s1,  H, (float)S*H);
    C2 b2=crot<S>(s2);
    C2 b3=cmulc(s3, -H, (float)S*H);
    C2 c0=cadd(a0,a2), c1=cadd(a1,a3), d0=csub(a0,a2), d1=crot<S>(csub(a1,a3));
    C2 e0=cadd(b0,b2), e1=cadd(b1,b3), f0=csub(b0,b2), f1=crot<S>(csub(b1,b3));
    r[0]=cadd(c0,c1); r[4]=csub(c0,c1);
    r[2]=cadd(d0,d1); r[6]=csub(d0,d1);
    r[1]=cadd(e0,e1); r[5]=csub(e0,e1);
    r[3]=cadd(f0,f1); r[7]=csub(f0,f1);
}

// per-thread twiddles: tw[d-1] = exp(+i*2*pi*t*d/64), d=1..7
__device__ __forceinline__ void make_tw(C2 tw[7], int t) {
    float ang = (6.28318530717958647692f/64.f) * (float)t;
    float s, c; __sincosf(ang, &s, &c);
    tw[0] = C2{c, s};
#pragma unroll
    for (int d=1; d<7; d++)
        tw[d] = C2{tw[d-1].re*c - tw[d-1].im*s, tw[d-1].re*s + tw[d-1].im*c};
}

template<int S>
__device__ __forceinline__ void apply_tw(C2 r[8], const C2 tw[7]) {
#pragma unroll
    for (int d=1;d<8;d++){
        float cs = tw[d-1].re;
        float sn = (S == -1) ? -tw[d-1].im : tw[d-1].im;
        r[d] = cmulc(r[d], cs, sn);
    }
}

// 64-pt FFT, row-local (the 8 cooperating threads are consecutive in one warp).
// Sg = this row's 64-cell float2 scratch; pxor = (row&1)<<3 (bank-parity split).
template<int S>
__device__ __forceinline__ void fft64w(C2 r[8], float2* Sg, int t, int pxor, const C2 tw[7]) {
    fft8<S>(r);
    apply_tw<S>(r, tw);
    __syncwarp();
#pragma unroll
    for (int d=0;d<8;d++){ int p = (8*d + ((d+t)&7)) ^ pxor; Sg[p] = make_float2(r[d].re, r[d].im); }
    __syncwarp();
#pragma unroll
    for (int b=0;b<8;b++){ int p = (8*t + ((b+t)&7)) ^ pxor; float2 v = Sg[p]; r[b] = C2{v.x, v.y}; }
    __syncwarp();
    fft8<S>(r);
}

// 64-pt FFT, cross-warp (thread octet q, line id kz; 8 cooperating threads are
// tid = kz + 64*q). Transpose via T[p][kz] (64x64 float2 plane). Leading
// __syncthreads protects T against prior readers; trailing reader sync is the
// next call's leading sync (callers do no T writes between calls).
template<int S>
__device__ __forceinline__ void fft64x(C2 r[8], float2* T, int kz, int q, const C2 tw[7]) {
    fft8<S>(r);
    apply_tw<S>(r, tw);
    __syncthreads();
#pragma unroll
    for (int d=0;d<8;d++){ int p = 8*d + ((d+q)&7); T[p*64 + kz] = make_float2(r[d].re, r[d].im); }
    __syncthreads();
#pragma unroll
    for (int b=0;b<8;b++){ int p = 8*q + ((b+q)&7); float2 v = T[p*64 + kz]; r[b] = C2{v.x, v.y}; }
    fft8<S>(r);
}

// plane cell index with bank-parity xor (consistent store/load bijection)
__device__ __forceinline__ int pcidx(int row, int col) {
    return row*64 + (col ^ ((row&1)<<3));
}

// ---------------- per-batch affine parameters ----------------
__global__ void mats_kernel(const float* __restrict__ theta) {
    int b = threadIdx.x;
    if (b >= BN) return;
    float t0=theta[b*6+0], t1=theta[b*6+1], t2=theta[b*6+2];
    float t3=theta[b*6+3], t4=theta[b*6+4], t5=theta[b*6+5];
    float phi = t0*2.f*PI_F - PI_F;
    float th  = t1*2.f*PI_F - PI_F;
    float psi = t2*2.f*PI_F - PI_F;
    float cf=cosf(phi), sf=sinf(phi), ct=cosf(th), st=sinf(th), cp=cosf(psi), sp=sinf(psi);
    float r00 =  cf*ct*cp - sf*sp;
    float r01 =  sf*ct*cp + cf*sp;
    float r02 = -st*cp;
    float r10 = -cf*ct*sp - sf*cp;
    float r11 = -sf*ct*sp + cf*cp;
    float r12 =  st*sp;
    float r20 =  cf*st;
    float r21 =  sf*st;
    float r22 =  ct;
    const float s = 64.f/66.f;
    float l0 = (2.f*t3-1.f)*s, l1=(2.f*t4-1.f)*s, l2=(2.f*t5-1.f)*s;
    float* M = g_mats + b*12;
    M[0]=r00; M[1]=r01; M[2]=r02;
    M[3]=r10; M[4]=r11; M[5]=r12;
    M[6]=r20; M[7]=r21; M[8]=r22;
    M[9]  = -(r00*l0 + r01*l1 + r02*l2);
    M[10] = -(r10*l0 + r11*l1 + r12*l2);
    M[11] = -(r20*l0 + r21*l1 + r22*l2);
}

__device__ __forceinline__ void corner(float u, int hi, int& i0, int& i1, float& d) {
    float f = floorf(u);
    int ii = (int)f;
    i0 = min(max(ii, 0), hi);
    i1 = min(max(ii + 1, 0), hi);
    d = u - (float)i0;          // delta vs *clipped* lower corner (matches reference)
}

// ---------------- mask warp kernel: rotation only, 64 grid, clamp border; 2 voxels/thread ----------------
__global__ void warp_masks_kernel(const float* __restrict__ m1,
                                  const float* __restrict__ m2,
                                  float2* __restrict__ o1, float2* __restrict__ o2) {
    int idx2 = blockIdx.x*256 + threadIdx.x;      // pair index; voxel v = 2*idx2
    int v = idx2 << 1;
    int b = v >> 18;
    int rem = v & (VOX-1);
    int i = rem >> 12, j = (rem >> 6) & 63, k0 = rem & 63;   // k0 even; handles k0, k0+1
    const float* M = g_mats + b*12;
    float r00=M[0],r01=M[1],r02=M[2],r10=M[3],r11=M[4],r12=M[5],r20=M[6],r21=M[7],r22=M[8];
    int base = b << 18;
    const float* p1 = m1 + base;
    const float* p2 = m2 + base;

    float gx = -1.f + (float)i*(2.f/63.f);
    float gy = -1.f + (float)j*(2.f/63.f);
    float bx = r00*gx + r01*gy;
    float by = r10*gx + r11*gy;
    float bz = r20*gx + r21*gy;

    float res1[2], res2[2];
#pragma unroll
    for (int kk=0; kk<2; kk++){
        float gz = -1.f + (float)(k0+kk)*(2.f/63.f);
        float sx = bx + r02*gz;
        float sy = by + r12*gz;
        float sz = bz + r22*gz;
        float ux = (sx+1.f)*31.5f, uy=(sy+1.f)*31.5f, uz=(sz+1.f)*31.5f;
        int x0,x1,y0,y1,z0,z1; float dx,dy,dz;
        corner(ux,63,x0,x1,dx); corner(uy,63,y0,y1,dy); corner(uz,63,z0,z1,dz);
        float wx0=1.f-dx, wy0=1.f-dy, wz0=1.f-dz;
        int i000=(x0<<12)+(y0<<6)+z0, i001=(x0<<12)+(y0<<6)+z1;
        int i010=(x0<<12)+(y1<<6)+z0, i011=(x0<<12)+(y1<<6)+z1;
        int i100=(x1<<12)+(y0<<6)+z0, i101=(x1<<12)+(y0<<6)+z1;
        int i110=(x1<<12)+(y1<<6)+z0, i111=(x1<<12)+(y1<<6)+z1;
        float w000=wx0*wy0*wz0, w001=wx0*wy0*dz, w010=wx0*dy*wz0, w011=wx0*dy*dz;
        float w100=dx*wy0*wz0,  w101=dx*wy0*dz,  w110=dx*dy*wz0,  w111=dx*dy*dz;
        res1[kk] = w000*p1[i000]+w001*p1[i001]+w010*p1[i010]+w011*p1[i011]
                 + w100*p1[i100]+w101*p1[i101]+w110*p1[i110]+w111*p1[i111];
        res2[kk] = w000*p2[i000]+w001*p2[i001]+w010*p2[i010]+w011*p2[i011]
                 + w100*p2[i100]+w101*p2[i101]+w110*p2[i110]+w111*p2[i111];
    }
    o1[idx2] = make_float2(res1[0], res1[1]);
    o2[idx2] = make_float2(res2[0], res2[1]);
}

// ---------------- FFT kernel A: warp X inline, pack W = X_t + i*Y, forward z then y ----------------
// smem: one 64x64 float2 plane (32KB), reused as pass-1 scratch, inter-pass plane, pass-2 transpose.
__global__ void __launch_bounds__(512, 2) fftA_kernel(const float* __restrict__ X,
                                                      const float* __restrict__ Y) {
    extern __shared__ float2 s[];          // 4096 float2
    int bx = blockIdx.x;                  // b*64 + x
    int b = bx >> 6, x = bx & 63;
    int tid = threadIdx.x;
    int g = tid>>3, t = tid&7;            // pass-1: row y=g, octet t (same warp)

    const float* M = g_mats + b*12;
    float r00=M[0],r01=M[1],r02=M[2],r10=M[3],r11=M[4],r12=M[5],r20=M[6],r21=M[7],r22=M[8];
    float c0=M[9],c1=M[10],c2=M[11];
    const float* Xb = X + ((size_t)b << 18);
    const float* Yb = Y + ((size_t)bx << 12);

    // padded-66 grid coords for this (x, y=g) line; z = 8a+t
    float gxc = -1.f + (float)(x+1)*(2.f/65.f);
    float gyc = -1.f + (float)(g+1)*(2.f/65.f);
    float bxs = r00*gxc + r01*gyc + c0;
    float bys = r10*gxc + r11*gyc + c1;
    float bzs = r20*gxc + r21*gyc + c2;

    C2 r[8];
#pragma unroll
    for (int a=0;a<8;a++){
        int z = 8*a + t;
        float gzc = -1.f + (float)(z+1)*(2.f/65.f);
        float sx = bxs + r02*gzc;
        float sy = bys + r12*gzc;
        float sz = bzs + r22*gzc;
        float ux=(sx+1.f)*32.5f, uy=(sy+1.f)*32.5f, uz=(sz+1.f)*32.5f;
        int x0,x1,y0,y1,z0,z1; float dx,dy,dz;
        corner(ux,65,x0,x1,dx); corner(uy,65,y0,y1,dy); corner(uz,65,z0,z1,dz);
        float wx0=1.f-dx, wy0=1.f-dy, wz0=1.f-dz;
        auto fetch = [&](int p,int q,int rr)->float{
            if ((unsigned)(p-1)<64u && (unsigned)(q-1)<64u && (unsigned)(rr-1)<64u)
                return Xb[((p-1)<<12) + ((q-1)<<6) + (rr-1)];
            return 0.f;
        };
        float v = wx0*wy0*wz0*fetch(x0,y0,z0) + wx0*wy0*dz*fetch(x0,y0,z1)
                + wx0*dy*wz0*fetch(x0,y1,z0)  + wx0*dy*dz*fetch(x0,y1,z1)
                + dx*wy0*wz0*fetch(x1,y0,z0)  + dx*wy0*dz*fetch(x1,y0,z1)
                + dx*dy*wz0*fetch(x1,y1,z0)   + dx*dy*dz*fetch(x1,y1,z1);
        float yv = Yb[(g<<6) + z];
        r[a] = C2{v, yv};                 // W = X_t + i*Y
    }

    C2 tw[7]; make_tw(tw, t);
    fft64w<-1>(r, s + g*64, t, (g&1)<<3, tw);     // forward z (row-local)
#pragma unroll
    for (int c=0;c<8;c++) s[pcidx(g, 8*c+t)] = make_float2(r[c].re, r[c].im);
    __syncthreads();

    // pass 2: forward y. remap: q = octet, kz = line id
    int q = tid>>6, kz = tid&63;
#pragma unroll
    for (int a=0;a<8;a++){ float2 v = s[pcidx(8*a+q, kz)]; r[a] = C2{v.x, v.y}; }
    C2 tw2[7]; make_tw(tw2, q);
    fft64x<-1>(r, s, kz, q, tw2);                 // leading sync protects plane reads

    float2* dst = g_fw + ((size_t)bx << 12);
#pragma unroll
    for (int c=0;c<8;c++) dst[(8*c+q)*64 + kz] = make_float2(r[c].re, r[c].im);
}

// ---------------- FFT kernel B: fwd-x, pointwise Z*E (symmetrized masks), inv-x ----------------
// Fully register-resident: coalesced direct loads/stores; smem only for transposes.
// E[k] = 0.5*((w1[k]+w1[-k]) - i*(w2[k]+w2[-k])), w_i[k] = M_i_t[(k+32) mod 64 per axis]
__global__ void __launch_bounds__(512, 2) fftB_kernel(const float* __restrict__ m1t,
                                                      const float* __restrict__ m2t) {
    extern __shared__ float2 s[];          // 4096 float2 transpose plane
    int bid = blockIdx.x;                 // b*64 + ky
    int b = bid >> 6, y = bid & 63;
    int tid = threadIdx.x;
    int q = tid>>6, kz = tid&63;          // line kz along x, octet q

    size_t base = ((size_t)b << 18);
    size_t ybase = base + ((size_t)y << 6);
    int ys  = y ^ 32;
    int ys2 = (32 - y) & 63;

    // spectrum: direct coalesced loads in consumption order
    C2 r[8];
#pragma unroll
    for (int a=0;a<8;a++){
        float2 v = g_fw[ybase + ((size_t)(8*a+q)<<12) + kz];
        r[a] = C2{v.x, v.y};
    }
    // masks: direct coalesced loads; combine to E in regs
    float er[8], ei[8];
    {
        int zs  = kz ^ 32;
        int zs2 = (32 - kz) & 63;
#pragma unroll
        for (int c=0;c<8;c++){
            int kx  = 8*c + q;
            int xs  = kx ^ 32;
            int xs2 = (32 - kx) & 63;
            size_t o1 = base + ((size_t)xs <<12) + (ys <<6) + zs;
            size_t o2 = base + ((size_t)xs2<<12) + (ys2<<6) + zs2;
            er[c] =  0.5f*(m1t[o1] + m1t[o2]);
            ei[c] = -0.5f*(m2t[o1] + m2t[o2]);
        }
    }

    C2 tw[7]; make_tw(tw, q);
    fft64x<-1>(r, s, kz, q, tw);          // forward x
#pragma unroll
    for (int c=0;c<8;c++) r[c] = cmulc(r[c], er[c], ei[c]);
    fft64x<1>(r, s, kz, q, tw);           // inverse x

#pragma unroll
    for (int c=0;c<8;c++)
        g_fw[ybase + ((size_t)(8*c+q)<<12) + kz] = make_float2(r[c].re, r[c].im);
}

// ---------------- FFT kernel C: inverse z then y, scale, real part ----------------
__global__ void __launch_bounds__(512, 2) fftC_kernel(float* __restrict__ out0) {
    extern __shared__ float2 s[];          // 4096 float2
    int bx = blockIdx.x;
    int tid = threadIdx.x;
    int g = tid>>3, t = tid&7;

    const float2* src = g_fw + ((size_t)bx << 12);
    C2 r[8];
#pragma unroll
    for (int a=0;a<8;a++){
        float2 v = src[(g<<6) + 8*a + t];
        r[a] = C2{v.x, v.y};
    }
    C2 tw[7]; make_tw(tw, t);
    fft64w<1>(r, s + g*64, t, (g&1)<<3, tw);      // inverse z (row-local)
#pragma unroll
    for (int c=0;c<8;c++) s[pcidx(g, 8*c+t)] = make_float2(r[c].re, r[c].im);
    __syncthreads();

    // pass 2: inverse y
    int q = tid>>6, kz = tid&63;
#pragma unroll
    for (int a=0;a<8;a++){ float2 v = s[pcidx(8*a+q, kz)]; r[a] = C2{v.x, v.y}; }
    C2 tw2[7]; make_tw(tw2, q);
    fft64x<1>(r, s, kz, q, tw2);

    const float sc = 1.f/262144.f;   // 1/64^3
    float* dst = out0 + ((size_t)bx << 12);
#pragma unroll
    for (int c=0;c<8;c++) dst[(8*c+q)*64 + kz] = r[c].re * sc;
}

// ---------------- launcher ----------------
extern "C" void kernel_launch(void* const* d_in, const int* in_sizes, int n_in,
                              void* d_out, int out_size) {
    const float* X  = (const float*)d_in[0];
    const float* Y  = (const float*)d_in[1];
    const float* m1 = (const float*)d_in[2];
    const float* m2 = (const float*)d_in[3];
    const float* th = (const float*)d_in[4];
    float* out0 = (float*)d_out;                 // real(ifft(...))
    float* out1 = out0 + (size_t)BN*VOX;         // M1_t
    float* out2 = out1 + (size_t)BN*VOX;         // M2_t

    const int SM = 4096 * 8;   // 32,768 B: one 64x64 float2 plane

    mats_kernel<<<1, 32>>>(th);
    warp_masks_kernel<<<(BN*VOX)/512, 256>>>(m1, m2, (float2*)out1, (float2*)out2);
    fftA_kernel<<<BN*NN, 512, SM>>>(X, Y);        // warp X + pack + z,y FFT -> g_fw
    fftB_kernel<<<BN*NN, 512, SM>>>(out1, out2);  // x FFT + Z*E + x IFFT (reg-resident)
    fftC_kernel<<<BN*NN, 512, SM>>>(out0);        // z,y IFFT + scale + real
}

// round 8
// speedup vs baseline: 1.1454x; 1.1122x over previous
#include <cuda_runtime.h>

#define PI_F 3.14159265358979323846f

#define BN 32
#define NN 64
#define VOX (NN*NN*NN)      // 262144

// ---------------- scratch (static device globals; no allocation allowed) ----------------
__device__ float2 g_fw[BN*VOX];          // packed spectrum Z = FFT(X_t + i*Y); reused for Z*E

// ---------------- complex helpers ----------------
struct C2 { float re, im; };
__device__ __forceinline__ C2 cadd(C2 a, C2 b){ return C2{a.re+b.re, a.im+b.im}; }
__device__ __forceinline__ C2 csub(C2 a, C2 b){ return C2{a.re-b.re, a.im-b.im}; }
__device__ __forceinline__ C2 cmulc(C2 a, float br, float bi){ return C2{a.re*br - a.im*bi, a.re*bi + a.im*br}; }
template<int S>
__device__ __forceinline__ C2 crot(C2 x){   // multiply by (0, S)
    return (S == -1) ? C2{x.im, -x.re} : C2{-x.im, x.re};
}

// 8-point DFT, natural order in/out, sign S (-1 fwd, +1 inv)
template<int S>
__device__ __forceinline__ void fft8(C2 r[8]) {
    const float H = 0.70710678118654752440f;
    C2 a0=cadd(r[0],r[4]), a1=cadd(r[1],r[5]), a2=cadd(r[2],r[6]), a3=cadd(r[3],r[7]);
    C2 s0=csub(r[0],r[4]), s1=csub(r[1],r[5]), s2=csub(r[2],r[6]), s3=csub(r[3],r[7]);
    C2 b0=s0;
    C2 b1=cmulc(s1,  H, (float)S*H);
    C2 b2=crot<S>(s2);
    C2 b3=cmulc(s3, -H, (float)S*H);
    C2 c0=cadd(a0,a2), c1=cadd(a1,a3), d0=csub(a0,a2), d1=crot<S>(csub(a1,a3));
    C2 e0=cadd(b0,b2), e1=cadd(b1,b3), f0=csub(b0,b2), f1=crot<S>(csub(b1,b3));
    r[0]=cadd(c0,c1); r[4]=csub(c0,c1);
    r[2]=cadd(d0,d1); r[6]=csub(d0,d1);
    r[1]=cadd(e0,e1); r[5]=csub(e0,e1);
    r[3]=cadd(f0,f1); r[7]=csub(f0,f1);
}

// per-thread twiddles: tw[d-1] = exp(+i*2*pi*t*d/64), d=1..7
__device__ __forceinline__ void make_tw(C2 tw[7], int t) {
    float ang = (6.28318530717958647692f/64.f) * (float)t;
    float s, c; __sincosf(ang, &s, &c);
    tw[0] = C2{c, s};
#pragma unroll
    for (int d=1; d<7; d++)
        tw[d] = C2{tw[d-1].re*c - tw[d-1].im*s, tw[d-1].re*s + tw[d-1].im*c};
}

template<int S>
__device__ __forceinline__ void apply_tw(C2 r[8], const C2 tw[7]) {
#pragma unroll
    for (int d=1;d<8;d++){
        float cs = tw[d-1].re;
        float sn = (S == -1) ? -tw[d-1].im : tw[d-1].im;
        r[d] = cmulc(r[d], cs, sn);
    }
}

// 64-pt FFT, row-local (the 8 cooperating threads are consecutive in one warp).
// Sg = this row's 64-cell float2 scratch; pxor = (row&1)<<3 (bank-parity split).
template<int S>
__device__ __forceinline__ void fft64w(C2 r[8], float2* Sg, int t, int pxor, const C2 tw[7]) {
    fft8<S>(r);
    apply_tw<S>(r, tw);
    __syncwarp();
#pragma unroll
    for (int d=0;d<8;d++){ int p = (8*d + ((d+t)&7)) ^ pxor; Sg[p] = make_float2(r[d].re, r[d].im); }
    __syncwarp();
#pragma unroll
    for (int b=0;b<8;b++){ int p = (8*t + ((b+t)&7)) ^ pxor; float2 v = Sg[p]; r[b] = C2{v.x, v.y}; }
    __syncwarp();
    fft8<S>(r);
}

// 64-pt FFT, cross-warp (thread octet q, line id kz; 8 cooperating threads are
// tid = kz + 64*q). Transpose via T[p][kz] (64x64 float2 plane). Leading
// __syncthreads protects T against prior readers.
template<int S>
__device__ __forceinline__ void fft64x(C2 r[8], float2* T, int kz, int q, const C2 tw[7]) {
    fft8<S>(r);
    apply_tw<S>(r, tw);
    __syncthreads();
#pragma unroll
    for (int d=0;d<8;d++){ int p = 8*d + ((d+q)&7); T[p*64 + kz] = make_float2(r[d].re, r[d].im); }
    __syncthreads();
#pragma unroll
    for (int b=0;b<8;b++){ int p = 8*q + ((b+q)&7); float2 v = T[p*64 + kz]; r[b] = C2{v.x, v.y}; }
    fft8<S>(r);
}

// plane cell index with bank-parity xor (consistent store/load bijection)
__device__ __forceinline__ int pcidx(int row, int col) {
    return row*64 + (col ^ ((row&1)<<3));
}

__device__ __forceinline__ void corner(float u, int hi, int& i0, int& i1, float& d) {
    float f = floorf(u);
    int ii = (int)f;
    i0 = min(max(ii, 0), hi);
    i1 = min(max(ii + 1, 0), hi);
    d = u - (float)i0;          // delta vs *clipped* lower corner (matches reference)
}

// per-thread affine params from theta (cheap; every thread redundantly)
__device__ __forceinline__ void make_mat(const float* __restrict__ theta, int b,
                                         float R[9], float C[3]) {
    float t0=theta[b*6+0], t1=theta[b*6+1], t2=theta[b*6+2];
    float t3=theta[b*6+3], t4=theta[b*6+4], t5=theta[b*6+5];
    float phi = t0*2.f*PI_F - PI_F;
    float th  = t1*2.f*PI_F - PI_F;
    float psi = t2*2.f*PI_F - PI_F;
    float cf=cosf(phi), sf=sinf(phi), ct=cosf(th), st=sinf(th), cp=cosf(psi), sp=sinf(psi);
    R[0] =  cf*ct*cp - sf*sp;
    R[1] =  sf*ct*cp + cf*sp;
    R[2] = -st*cp;
    R[3] = -cf*ct*sp - sf*cp;
    R[4] = -sf*ct*sp + cf*cp;
    R[5] =  st*sp;
    R[6] =  cf*st;
    R[7] =  sf*st;
    R[8] =  ct;
    const float s = 64.f/66.f;
    float l0 = (2.f*t3-1.f)*s, l1=(2.f*t4-1.f)*s, l2=(2.f*t5-1.f)*s;
    C[0] = -(R[0]*l0 + R[1]*l1 + R[2]*l2);
    C[1] = -(R[3]*l0 + R[4]*l1 + R[5]*l2);
    C[2] = -(R[6]*l0 + R[7]*l1 + R[8]*l2);
}

// ---------------- merged kernel A: mask warp (this plane) + X warp + pack + fwd z,y FFT ----------------
// Block = one (b,x) plane. Phase 0: warp m1/m2 for plane i=x (coalesced stores to outputs).
// Phase 1: inline X gather + W = X_t + i*Y, forward FFT z then y -> g_fw.
// No sync between phases: gather-stalled warps overlap FFT-compute warps.
__global__ void __launch_bounds__(512, 2) fftA_kernel(const float* __restrict__ X,
                                                      const float* __restrict__ Y,
                                                      const float* __restrict__ m1,
                                                      const float* __restrict__ m2,
                                                      const float* __restrict__ theta,
                                                      float* __restrict__ o1,
                                                      float* __restrict__ o2) {
    extern __shared__ float2 s[];          // 4096 float2
    int bx = blockIdx.x;                  // b*64 + x
    int b = bx >> 6, x = bx & 63;
    int tid = threadIdx.x;

    float R[9], C[3];
    make_mat(theta, b, R, C);
    int base = b << 18;

    // ---- phase 0: mask warp for output plane i = x (rotation only, 64-grid, clamp) ----
    {
        const float* p1 = m1 + base;
        const float* p2 = m2 + base;
        float gx = -1.f + (float)x*(2.f/63.f);
        float bxm = R[0]*gx, bym = R[3]*gx, bzm = R[6]*gx;
        for (int ii=0; ii<8; ii++){
            int idx = tid + ii*512;
            int j = idx>>6, k = idx&63;
            float gy = -1.f + (float)j*(2.f/63.f);
            float gz = -1.f + (float)k*(2.f/63.f);
            float sx = bxm + R[1]*gy + R[2]*gz;
            float sy = bym + R[4]*gy + R[5]*gz;
            float sz = bzm + R[7]*gy + R[8]*gz;
            float ux = (sx+1.f)*31.5f, uy=(sy+1.f)*31.5f, uz=(sz+1.f)*31.5f;
            int x0,x1,y0,y1,z0,z1; float dx,dy,dz;
            corner(ux,63,x0,x1,dx); corner(uy,63,y0,y1,dy); corner(uz,63,z0,z1,dz);
            float wx0=1.f-dx, wy0=1.f-dy, wz0=1.f-dz;
            int i000=(x0<<12)+(y0<<6)+z0, i001=(x0<<12)+(y0<<6)+z1;
            int i010=(x0<<12)+(y1<<6)+z0, i011=(x0<<12)+(y1<<6)+z1;
            int i100=(x1<<12)+(y0<<6)+z0, i101=(x1<<12)+(y0<<6)+z1;
            int i110=(x1<<12)+(y1<<6)+z0, i111=(x1<<12)+(y1<<6)+z1;
            float w000=wx0*wy0*wz0, w001=wx0*wy0*dz, w010=wx0*dy*wz0, w011=wx0*dy*dz;
            float w100=dx*wy0*wz0,  w101=dx*wy0*dz,  w110=dx*dy*wz0,  w111=dx*dy*dz;
            float v1 = w000*p1[i000]+w001*p1[i001]+w010*p1[i010]+w011*p1[i011]
                     + w100*p1[i100]+w101*p1[i101]+w110*p1[i110]+w111*p1[i111];
            float v2 = w000*p2[i000]+w001*p2[i001]+w010*p2[i010]+w011*p2[i011]
                     + w100*p2[i100]+w101*p2[i101]+w110*p2[i110]+w111*p2[i111];
            int oidx = base + (x<<12) + idx;
            o1[oidx] = v1;
            o2[oidx] = v2;
        }
    }

    // ---- phase 1: X warp + pack + forward FFT ----
    int g = tid>>3, t = tid&7;            // pass-1: row y=g, octet t (same warp)
    const float* Xb = X + ((size_t)b << 18);
    const float* Yb = Y + ((size_t)bx << 12);

    // padded-66 grid coords for this (x, y=g) line; z = 8a+t
    float gxc = -1.f + (float)(x+1)*(2.f/65.f);
    float gyc = -1.f + (float)(g+1)*(2.f/65.f);
    float bxs = R[0]*gxc + R[1]*gyc + C[0];
    float bys = R[3]*gxc + R[4]*gyc + C[1];
    float bzs = R[6]*gxc + R[7]*gyc + C[2];

    C2 r[8];
#pragma unroll
    for (int a=0;a<8;a++){
        int z = 8*a + t;
        float gzc = -1.f + (float)(z+1)*(2.f/65.f);
        float sx = bxs + R[2]*gzc;
        float sy = bys + R[5]*gzc;
        float sz = bzs + R[8]*gzc;
        float ux=(sx+1.f)*32.5f, uy=(sy+1.f)*32.5f, uz=(sz+1.f)*32.5f;
        int x0,x1,y0,y1,z0,z1; float dx,dy,dz;
        corner(ux,65,x0,x1,dx); corner(uy,65,y0,y1,dy); corner(uz,65,z0,z1,dz);
        float wx0=1.f-dx, wy0=1.f-dy, wz0=1.f-dz;
        auto fetch = [&](int p,int q,int rr)->float{
            if ((unsigned)(p-1)<64u && (unsigned)(q-1)<64u && (unsigned)(rr-1)<64u)
                return Xb[((p-1)<<12) + ((q-1)<<6) + (rr-1)];
            return 0.f;
        };
        float v = wx0*wy0*wz0*fetch(x0,y0,z0) + wx0*wy0*dz*fetch(x0,y0,z1)
                + wx0*dy*wz0*fetch(x0,y1,z0)  + wx0*dy*dz*fetch(x0,y1,z1)
                + dx*wy0*wz0*fetch(x1,y0,z0)  + dx*wy0*dz*fetch(x1,y0,z1)
                + dx*dy*wz0*fetch(x1,y1,z0)   + dx*dy*dz*fetch(x1,y1,z1);
        float yv = Yb[(g<<6) + z];
        r[a] = C2{v, yv};                 // W = X_t + i*Y
    }

    C2 tw[7]; make_tw(tw, t);
    fft64w<-1>(r, s + g*64, t, (g&1)<<3, tw);     // forward z (row-local)
#pragma unroll
    for (int c=0;c<8;c++) s[pcidx(g, 8*c+t)] = make_float2(r[c].re, r[c].im);
    __syncthreads();

    // pass 2: forward y. remap: q = octet, kz = line id
    int q = tid>>6, kz = tid&63;
#pragma unroll
    for (int a=0;a<8;a++){ float2 v = s[pcidx(8*a+q, kz)]; r[a] = C2{v.x, v.y}; }
    C2 tw2[7]; make_tw(tw2, q);
    fft64x<-1>(r, s, kz, q, tw2);

    float2* dst = g_fw + ((size_t)bx << 12);
#pragma unroll
    for (int c=0;c<8;c++) dst[(8*c+q)*64 + kz] = make_float2(r[c].re, r[c].im);
}

// ---------------- FFT kernel B: fwd-x, pointwise Z*E (symmetrized masks), inv-x ----------------
// Fully register-resident: coalesced direct loads/stores; smem only for transposes.
// E[k] = 0.5*((w1[k]+w1[-k]) - i*(w2[k]+w2[-k])), w_i[k] = M_i_t[(k+32) mod 64 per axis]
__global__ void __launch_bounds__(512, 2) fftB_kernel(const float* __restrict__ m1t,
                                                      const float* __restrict__ m2t) {
    extern __shared__ float2 s[];          // 4096 float2 transpose plane
    int bid = blockIdx.x;                 // b*64 + ky
    int b = bid >> 6, y = bid & 63;
    int tid = threadIdx.x;
    int q = tid>>6, kz = tid&63;          // line kz along x, octet q

    size_t base = ((size_t)b << 18);
    size_t ybase = base + ((size_t)y << 6);
    int ys  = y ^ 32;
    int ys2 = (32 - y) & 63;

    // spectrum: direct coalesced loads in consumption order
    C2 r[8];
#pragma unroll
    for (int a=0;a<8;a++){
        float2 v = g_fw[ybase + ((size_t)(8*a+q)<<12) + kz];
        r[a] = C2{v.x, v.y};
    }
    // masks: direct coalesced loads; combine to E in regs
    float er[8], ei[8];
    {
        int zs  = kz ^ 32;
        int zs2 = (32 - kz) & 63;
#pragma unroll
        for (int c=0;c<8;c++){
            int kx  = 8*c + q;
            int xs  = kx ^ 32;
            int xs2 = (32 - kx) & 63;
            size_t o1 = base + ((size_t)xs <<12) + (ys <<6) + zs;
            size_t o2 = base + ((size_t)xs2<<12) + (ys2<<6) + zs2;
            er[c] =  0.5f*(m1t[o1] + m1t[o2]);
            ei[c] = -0.5f*(m2t[o1] + m2t[o2]);
        }
    }

    C2 tw[7]; make_tw(tw, q);
    fft64x<-1>(r, s, kz, q, tw);          // forward x
#pragma unroll
    for (int c=0;c<8;c++) r[c] = cmulc(r[c], er[c], ei[c]);
    fft64x<1>(r, s, kz, q, tw);           // inverse x

#pragma unroll
    for (int c=0;c<8;c++)
        g_fw[ybase + ((size_t)(8*c+q)<<12) + kz] = make_float2(r[c].re, r[c].im);
}

// ---------------- FFT kernel C: inverse z then y, scale, real part ----------------
__global__ void __launch_bounds__(512, 2) fftC_kernel(float* __restrict__ out0) {
    extern __shared__ float2 s[];          // 4096 float2
    int bx = blockIdx.x;
    int tid = threadIdx.x;
    int g = tid>>3, t = tid&7;

    const float2* src = g_fw + ((size_t)bx << 12);
    C2 r[8];
#pragma unroll
    for (int a=0;a<8;a++){
        float2 v = src[(g<<6) + 8*a + t];
        r[a] = C2{v.x, v.y};
    }
    C2 tw[7]; make_tw(tw, t);
    fft64w<1>(r, s + g*64, t, (g&1)<<3, tw);      // inverse z (row-local)
#pragma unroll
    for (int c=0;c<8;c++) s[pcidx(g, 8*c+t)] = make_float2(r[c].re, r[c].im);
    __syncthreads();

    // pass 2: inverse y
    int q = tid>>6, kz = tid&63;
#pragma unroll
    for (int a=0;a<8;a++){ float2 v = s[pcidx(8*a+q, kz)]; r[a] = C2{v.x, v.y}; }
    C2 tw2[7]; make_tw(tw2, q);
    fft64x<1>(r, s, kz, q, tw2);

    const float sc = 1.f/262144.f;   // 1/64^3
    float* dst = out0 + ((size_t)bx << 12);
#pragma unroll
    for (int c=0;c<8;c++) dst[(8*c+q)*64 + kz] = r[c].re * sc;
}

// ---------------- launcher ----------------
extern "C" void kernel_launch(void* const* d_in, const int* in_sizes, int n_in,
                              void* d_out, int out_size) {
    const float* X  = (const float*)d_in[0];
    const float* Y  = (const float*)d_in[1];
    const float* m1 = (const float*)d_in[2];
    const float* m2 = (const float*)d_in[3];
    const float* th = (const float*)d_in[4];
    float* out0 = (float*)d_out;                 // real(ifft(...))
    float* out1 = out0 + (size_t)BN*VOX;         // M1_t
    float* out2 = out1 + (size_t)BN*VOX;         // M2_t

    const int SM = 4096 * 8;   // 32,768 B: one 64x64 float2 plane

    fftA_kernel<<<BN*NN, 512, SM>>>(X, Y, m1, m2, th, out1, out2); // masks + X warp + fwd FFT
    fftB_kernel<<<BN*NN, 512, SM>>>(out1, out2);                   // x FFT + Z*E + x IFFT
    fftC_kernel<<<BN*NN, 512, SM>>>(out0);                         // z,y IFFT + real
}

// round 9
// speedup vs baseline: 1.3352x; 1.1656x over previous
#include <cuda_runtime.h>

#define PI_F 3.14159265358979323846f

#define BN 32
#define NN 64
#define VOX (NN*NN*NN)      // 262144

// ---------------- scratch (static device globals; no allocation allowed) ----------------
__device__ float2 g_fw[BN*VOX];          // packed spectrum Z = FFT(X_t + i*Y); reused for Z*E
__device__ float2 g_m12[BN*VOX];         // interleaved masks (m1, m2) for single-load gather

// ---------------- complex helpers ----------------
struct C2 { float re, im; };
__device__ __forceinline__ C2 cadd(C2 a, C2 b){ return C2{a.re+b.re, a.im+b.im}; }
__device__ __forceinline__ C2 csub(C2 a, C2 b){ return C2{a.re-b.re, a.im-b.im}; }
__device__ __forceinline__ C2 cmulc(C2 a, float br, float bi){ return C2{a.re*br - a.im*bi, a.re*bi + a.im*br}; }
template<int S>
__device__ __forceinline__ C2 crot(C2 x){   // multiply by (0, S)
    return (S == -1) ? C2{x.im, -x.re} : C2{-x.im, x.re};
}

// 8-point DFT, natural order in/out, sign S (-1 fwd, +1 inv)
template<int S>
__device__ __forceinline__ void fft8(C2 r[8]) {
    const float H = 0.70710678118654752440f;
    C2 a0=cadd(r[0],r[4]), a1=cadd(r[1],r[5]), a2=cadd(r[2],r[6]), a3=cadd(r[3],r[7]);
    C2 s0=csub(r[0],r[4]), s1=csub(r[1],r[5]), s2=csub(r[2],r[6]), s3=csub(r[3],r[7]);
    C2 b0=s0;
    C2 b1=cmulc(s1,  H, (float)S*H);
    C2 b2=crot<S>(s2);
    C2 b3=cmulc(s3, -H, (float)S*H);
    C2 c0=cadd(a0,a2), c1=cadd(a1,a3), d0=csub(a0,a2), d1=crot<S>(csub(a1,a3));
    C2 e0=cadd(b0,b2), e1=cadd(b1,b3), f0=csub(b0,b2), f1=crot<S>(csub(b1,b3));
    r[0]=cadd(c0,c1); r[4]=csub(c0,c1);
    r[2]=cadd(d0,d1); r[6]=csub(d0,d1);
    r[1]=cadd(e0,e1); r[5]=csub(e0,e1);
    r[3]=cadd(f0,f1); r[7]=csub(f0,f1);
}

// per-thread twiddles: tw[d-1] = exp(+i*2*pi*t*d/64), d=1..7
__device__ __forceinline__ void make_tw(C2 tw[7], int t) {
    float ang = (6.28318530717958647692f/64.f) * (float)t;
    float s, c; __sincosf(ang, &s, &c);
    tw[0] = C2{c, s};
#pragma unroll
    for (int d=1; d<7; d++)
        tw[d] = C2{tw[d-1].re*c - tw[d-1].im*s, tw[d-1].re*s + tw[d-1].im*c};
}

template<int S>
__device__ __forceinline__ void apply_tw(C2 r[8], const C2 tw[7]) {
#pragma unroll
    for (int d=1;d<8;d++){
        float cs = tw[d-1].re;
        float sn = (S == -1) ? -tw[d-1].im : tw[d-1].im;
        r[d] = cmulc(r[d], cs, sn);
    }
}

// 64-pt FFT, row-local (the 8 cooperating threads are consecutive in one warp).
// Sg = this row's 64-cell float2 scratch; pxor = (row&1)<<3 (bank-parity split).
template<int S>
__device__ __forceinline__ void fft64w(C2 r[8], float2* Sg, int t, int pxor, const C2 tw[7]) {
    fft8<S>(r);
    apply_tw<S>(r, tw);
    __syncwarp();
#pragma unroll
    for (int d=0;d<8;d++){ int p = (8*d + ((d+t)&7)) ^ pxor; Sg[p] = make_float2(r[d].re, r[d].im); }
    __syncwarp();
#pragma unroll
    for (int b=0;b<8;b++){ int p = (8*t + ((b+t)&7)) ^ pxor; float2 v = Sg[p]; r[b] = C2{v.x, v.y}; }
    __syncwarp();
    fft8<S>(r);
}

// 64-pt FFT, cross-warp (thread octet q, line id kz; 8 cooperating threads are
// tid = kz + 64*q). Transpose via T[p][kz] (64x64 float2 plane). Leading
// __syncthreads protects T against prior readers.
template<int S>
__device__ __forceinline__ void fft64x(C2 r[8], float2* T, int kz, int q, const C2 tw[7]) {
    fft8<S>(r);
    apply_tw<S>(r, tw);
    __syncthreads();
#pragma unroll
    for (int d=0;d<8;d++){ int p = 8*d + ((d+q)&7); T[p*64 + kz] = make_float2(r[d].re, r[d].im); }
    __syncthreads();
#pragma unroll
    for (int b=0;b<8;b++){ int p = 8*q + ((b+q)&7); float2 v = T[p*64 + kz]; r[b] = C2{v.x, v.y}; }
    fft8<S>(r);
}

// plane cell index with bank-parity xor (consistent store/load bijection)
__device__ __forceinline__ int pcidx(int row, int col) {
    return row*64 + (col ^ ((row&1)<<3));
}

__device__ __forceinline__ void corner(float u, int hi, int& i0, int& i1, float& d) {
    float f = floorf(u);
    int ii = (int)f;
    i0 = min(max(ii, 0), hi);
    i1 = min(max(ii + 1, 0), hi);
    d = u - (float)i0;          // delta vs *clipped* lower corner (matches reference)
}

// per-thread affine params from theta (cheap; every thread redundantly)
__device__ __forceinline__ void make_mat(const float* __restrict__ theta, int b,
                                         float R[9], float C[3]) {
    float t0=theta[b*6+0], t1=theta[b*6+1], t2=theta[b*6+2];
    float t3=theta[b*6+3], t4=theta[b*6+4], t5=theta[b*6+5];
    float phi = t0*2.f*PI_F - PI_F;
    float th  = t1*2.f*PI_F - PI_F;
    float psi = t2*2.f*PI_F - PI_F;
    float cf=cosf(phi), sf=sinf(phi), ct=cosf(th), st=sinf(th), cp=cosf(psi), sp=sinf(psi);
    R[0] =  cf*ct*cp - sf*sp;
    R[1] =  sf*ct*cp + cf*sp;
    R[2] = -st*cp;
    R[3] = -cf*ct*sp - sf*cp;
    R[4] = -sf*ct*sp + cf*cp;
    R[5] =  st*sp;
    R[6] =  cf*st;
    R[7] =  sf*st;
    R[8] =  ct;
    const float s = 64.f/66.f;
    float l0 = (2.f*t3-1.f)*s, l1=(2.f*t4-1.f)*s, l2=(2.f*t5-1.f)*s;
    C[0] = -(R[0]*l0 + R[1]*l1 + R[2]*l2);
    C[1] = -(R[3]*l0 + R[4]*l1 + R[5]*l2);
    C[2] = -(R[6]*l0 + R[7]*l1 + R[8]*l2);
}

// ---------------- prepack kernel: interleave m1,m2 -> g_m12 (coalesced, float4) ----------------
__global__ void pack_masks_kernel(const float4* __restrict__ m1,
                                  const float4* __restrict__ m2) {
    int i4 = blockIdx.x*256 + threadIdx.x;        // quad index over BN*VOX/4
    float4 a = m1[i4];
    float4 b = m2[i4];
    float4* dst = (float4*)g_m12;
    dst[i4*2]   = make_float4(a.x, b.x, a.y, b.y);
    dst[i4*2+1] = make_float4(a.z, b.z, a.w, b.w);
}

// ---------------- merged kernel A: mask warp (this plane) + X warp + pack + fwd z,y FFT ----------------
// Block = one (b,x) plane. Phase 0: warp (m1,m2) for plane i=x via interleaved g_m12
// (8 LDG.64 per voxel). Phase 1: inline X gather + W = X_t + i*Y, forward FFT z,y -> g_fw.
__global__ void __launch_bounds__(512, 2) fftA_kernel(const float* __restrict__ X,
                                                      const float* __restrict__ Y,
                                                      const float* __restrict__ theta,
                                                      float* __restrict__ o1,
                                                      float* __restrict__ o2) {
    extern __shared__ float2 s[];          // 4096 float2
    int bx = blockIdx.x;                  // b*64 + x
    int b = bx >> 6, x = bx & 63;
    int tid = threadIdx.x;

    float R[9], C[3];
    make_mat(theta, b, R, C);
    int base = b << 18;

    // ---- phase 0: mask warp for output plane i = x (rotation only, 64-grid, clamp) ----
    {
        const float2* p12 = g_m12 + base;
        float gx = -1.f + (float)x*(2.f/63.f);
        float bxm = R[0]*gx, bym = R[3]*gx, bzm = R[6]*gx;
        for (int ii=0; ii<8; ii++){
            int idx = tid + ii*512;
            int j = idx>>6, k = idx&63;
            float gy = -1.f + (float)j*(2.f/63.f);
            float gz = -1.f + (float)k*(2.f/63.f);
            float sx = bxm + R[1]*gy + R[2]*gz;
            float sy = bym + R[4]*gy + R[5]*gz;
            float sz = bzm + R[7]*gy + R[8]*gz;
            float ux = (sx+1.f)*31.5f, uy=(sy+1.f)*31.5f, uz=(sz+1.f)*31.5f;
            int x0,x1,y0,y1,z0,z1; float dx,dy,dz;
            corner(ux,63,x0,x1,dx); corner(uy,63,y0,y1,dy); corner(uz,63,z0,z1,dz);
            float wx0=1.f-dx, wy0=1.f-dy, wz0=1.f-dz;
            float2 c000 = p12[(x0<<12)+(y0<<6)+z0];
            float2 c001 = p12[(x0<<12)+(y0<<6)+z1];
            float2 c010 = p12[(x0<<12)+(y1<<6)+z0];
            float2 c011 = p12[(x0<<12)+(y1<<6)+z1];
            float2 c100 = p12[(x1<<12)+(y0<<6)+z0];
            float2 c101 = p12[(x1<<12)+(y0<<6)+z1];
            float2 c110 = p12[(x1<<12)+(y1<<6)+z0];
            float2 c111 = p12[(x1<<12)+(y1<<6)+z1];
            float w000=wx0*wy0*wz0, w001=wx0*wy0*dz, w010=wx0*dy*wz0, w011=wx0*dy*dz;
            float w100=dx*wy0*wz0,  w101=dx*wy0*dz,  w110=dx*dy*wz0,  w111=dx*dy*dz;
            float v1 = w000*c000.x+w001*c001.x+w010*c010.x+w011*c011.x
                     + w100*c100.x+w101*c101.x+w110*c110.x+w111*c111.x;
            float v2 = w000*c000.y+w001*c001.y+w010*c010.y+w011*c011.y
                     + w100*c100.y+w101*c101.y+w110*c110.y+w111*c111.y;
            int oidx = base + (x<<12) + idx;
            o1[oidx] = v1;
            o2[oidx] = v2;
        }
    }

    // ---- phase 1: X warp + pack + forward FFT ----
    int g = tid>>3, t = tid&7;            // pass-1: row y=g, octet t (same warp)
    const float* Xb = X + ((size_t)b << 18);
    const float* Yb = Y + ((size_t)bx << 12);

    // padded-66 grid coords for this (x, y=g) line; z = 8a+t
    float gxc = -1.f + (float)(x+1)*(2.f/65.f);
    float gyc = -1.f + (float)(g+1)*(2.f/65.f);
    float bxs = R[0]*gxc + R[1]*gyc + C[0];
    float bys = R[3]*gxc + R[4]*gyc + C[1];
    float bzs = R[6]*gxc + R[7]*gyc + C[2];

    C2 r[8];
#pragma unroll
    for (int a=0;a<8;a++){
        int z = 8*a + t;
        float gzc = -1.f + (float)(z+1)*(2.f/65.f);
        float sx = bxs + R[2]*gzc;
        float sy = bys + R[5]*gzc;
        float sz = bzs + R[8]*gzc;
        float ux=(sx+1.f)*32.5f, uy=(sy+1.f)*32.5f, uz=(sz+1.f)*32.5f;
        int x0,x1,y0,y1,z0,z1; float dx,dy,dz;
        corner(ux,65,x0,x1,dx); corner(uy,65,y0,y1,dy); corner(uz,65,z0,z1,dz);
        float wx0=1.f-dx, wy0=1.f-dy, wz0=1.f-dz;
        auto fetch = [&](int p,int q,int rr)->float{
            if ((unsigned)(p-1)<64u && (unsigned)(q-1)<64u && (unsigned)(rr-1)<64u)
                return Xb[((p-1)<<12) + ((q-1)<<6) + (rr-1)];
            return 0.f;
        };
        float v = wx0*wy0*wz0*fetch(x0,y0,z0) + wx0*wy0*dz*fetch(x0,y0,z1)
                + wx0*dy*wz0*fetch(x0,y1,z0)  + wx0*dy*dz*fetch(x0,y1,z1)
                + dx*wy0*wz0*fetch(x1,y0,z0)  + dx*wy0*dz*fetch(x1,y0,z1)
                + dx*dy*wz0*fetch(x1,y1,z0)   + dx*dy*dz*fetch(x1,y1,z1);
        float yv = Yb[(g<<6) + z];
        r[a] = C2{v, yv};                 // W = X_t + i*Y
    }

    C2 tw[7]; make_tw(tw, t);
    fft64w<-1>(r, s + g*64, t, (g&1)<<3, tw);     // forward z (row-local)
#pragma unroll
    for (int c=0;c<8;c++) s[pcidx(g, 8*c+t)] = make_float2(r[c].re, r[c].im);
    __syncthreads();

    // pass 2: forward y. remap: q = octet, kz = line id
    int q = tid>>6, kz = tid&63;
#pragma unroll
    for (int a=0;a<8;a++){ float2 v = s[pcidx(8*a+q, kz)]; r[a] = C2{v.x, v.y}; }
    C2 tw2[7]; make_tw(tw2, q);
    fft64x<-1>(r, s, kz, q, tw2);

    float2* dst = g_fw + ((size_t)bx << 12);
#pragma unroll
    for (int c=0;c<8;c++) dst[(8*c+q)*64 + kz] = make_float2(r[c].re, r[c].im);
}

// ---------------- FFT kernel B: fwd-x, pointwise Z*E (symmetrized masks), inv-x ----------------
// Fully register-resident: coalesced direct loads/stores; smem only for transposes.
// E[k] = 0.5*((w1[k]+w1[-k]) - i*(w2[k]+w2[-k])), w_i[k] = M_i_t[(k+32) mod 64 per axis]
__global__ void __launch_bounds__(512, 2) fftB_kernel(const float* __restrict__ m1t,
                                                      const float* __restrict__ m2t) {
    extern __shared__ float2 s[];          // 4096 float2 transpose plane
    int bid = blockIdx.x;                 // b*64 + ky
    int b = bid >> 6, y = bid & 63;
    int tid = threadIdx.x;
    int q = tid>>6, kz = tid&63;          // line kz along x, octet q

    size_t base = ((size_t)b << 18);
    size_t ybase = base + ((size_t)y << 6);
    int ys  = y ^ 32;
    int ys2 = (32 - y) & 63;

    // spectrum: direct coalesced loads in consumption order
    C2 r[8];
#pragma unroll
    for (int a=0;a<8;a++){
        float2 v = g_fw[ybase + ((size_t)(8*a+q)<<12) + kz];
        r[a] = C2{v.x, v.y};
    }
    // masks: direct coalesced loads; combine to E in regs
    float er[8], ei[8];
    {
        int zs  = kz ^ 32;
        int zs2 = (32 - kz) & 63;
#pragma unroll
        for (int c=0;c<8;c++){
            int kx  = 8*c + q;
            int xs  = kx ^ 32;
            int xs2 = (32 - kx) & 63;
            size_t o1 = base + ((size_t)xs <<12) + (ys <<6) + zs;
            size_t o2 = base + ((size_t)xs2<<12) + (ys2<<6) + zs2;
            er[c] =  0.5f*(m1t[o1] + m1t[o2]);
            ei[c] = -0.5f*(m2t[o1] + m2t[o2]);
        }
    }

    C2 tw[7]; make_tw(tw, q);
    fft64x<-1>(r, s, kz, q, tw);          // forward x
#pragma unroll
    for (int c=0;c<8;c++) r[c] = cmulc(r[c], er[c], ei[c]);
    fft64x<1>(r, s, kz, q, tw);           // inverse x

#pragma unroll
    for (int c=0;c<8;c++)
        g_fw[ybase + ((size_t)(8*c+q)<<12) + kz] = make_float2(r[c].re, r[c].im);
}

// ---------------- FFT kernel C: inverse z then y, scale, real part ----------------
__global__ void __launch_bounds__(512, 2) fftC_kernel(float* __restrict__ out0) {
    extern __shared__ float2 s[];          // 4096 float2
    int bx = blockIdx.x;
    int tid = threadIdx.x;
    int g = tid>>3, t = tid&7;

    const float2* src = g_fw + ((size_t)bx << 12);
    C2 r[8];
#pragma unroll
    for (int a=0;a<8;a++){
        float2 v = src[(g<<6) + 8*a + t];
        r[a] = C2{v.x, v.y};
    }
    C2 tw[7]; make_tw(tw, t);
    fft64w<1>(r, s + g*64, t, (g&1)<<3, tw);      // inverse z (row-local)
#pragma unroll
    for (int c=0;c<8;c++) s[pcidx(g, 8*c+t)] = make_float2(r[c].re, r[c].im);
    __syncthreads();

    // pass 2: inverse y
    int q = tid>>6, kz = tid&63;
#pragma unroll
    for (int a=0;a<8;a++){ float2 v = s[pcidx(8*a+q, kz)]; r[a] = C2{v.x, v.y}; }
    C2 tw2[7]; make_tw(tw2, q);
    fft64x<1>(r, s, kz, q, tw2);

    const float sc = 1.f/262144.f;   // 1/64^3
    float* dst = out0 + ((size_t)bx << 12);
#pragma unroll
    for (int c=0;c<8;c++) dst[(8*c+q)*64 + kz] = r[c].re * sc;
}

// ---------------- launcher ----------------
extern "C" void kernel_launch(void* const* d_in, const int* in_sizes, int n_in,
                              void* d_out, int out_size) {
    const float* X  = (const float*)d_in[0];
    const float* Y  = (const float*)d_in[1];
    const float* m1 = (const float*)d_in[2];
    const float* m2 = (const float*)d_in[3];
    const float* th = (const float*)d_in[4];
    float* out0 = (float*)d_out;                 // real(ifft(...))
    float* out1 = out0 + (size_t)BN*VOX;         // M1_t
    float* out2 = out1 + (size_t)BN*VOX;         // M2_t

    const int SM = 4096 * 8;   // 32,768 B: one 64x64 float2 plane

    pack_masks_kernel<<<(BN*VOX/4)/256, 256>>>((const float4*)m1, (const float4*)m2);
    fftA_kernel<<<BN*NN, 512, SM>>>(X, Y, th, out1, out2);   // masks + X warp + fwd FFT
    fftB_kernel<<<BN*NN, 512, SM>>>(out1, out2);             // x FFT + Z*E + x IFFT
    fftC_kernel<<<BN*NN, 512, SM>>>(out0);                   // z,y IFFT + real
}

// round 10
// speedup vs baseline: 1.3571x; 1.0164x over previous
#include <cuda_runtime.h>

#define PI_F 3.14159265358979323846f

#define BN 32
#define NN 64
#define VOX (NN*NN*NN)      // 262144

// ---------------- scratch (static device globals; no allocation allowed) ----------------
__device__ float2 g_fw[BN*VOX];          // packed spectrum Z = FFT(X_t + i*Y); reused for Z*E
__device__ float4 g_m12p[BN*VOX];        // z-pair interleaved masks (m1[z],m2[z],m1[z+1],m2[z+1])

// ---------------- complex helpers ----------------
struct C2 { float re, im; };
__device__ __forceinline__ C2 cadd(C2 a, C2 b){ return C2{a.re+b.re, a.im+b.im}; }
__device__ __forceinline__ C2 csub(C2 a, C2 b){ return C2{a.re-b.re, a.im-b.im}; }
__device__ __forceinline__ C2 cmulc(C2 a, float br, float bi){ return C2{a.re*br - a.im*bi, a.re*bi + a.im*br}; }
template<int S>
__device__ __forceinline__ C2 crot(C2 x){   // multiply by (0, S)
    return (S == -1) ? C2{x.im, -x.re} : C2{-x.im, x.re};
}

// 8-point DFT, natural order in/out, sign S (-1 fwd, +1 inv)
template<int S>
__device__ __forceinline__ void fft8(C2 r[8]) {
    const float H = 0.70710678118654752440f;
    C2 a0=cadd(r[0],r[4]), a1=cadd(r[1],r[5]), a2=cadd(r[2],r[6]), a3=cadd(r[3],r[7]);
    C2 s0=csub(r[0],r[4]), s1=csub(r[1],r[5]), s2=csub(r[2],r[6]), s3=csub(r[3],r[7]);
    C2 b0=s0;
    C2 b1=cmulc(s1,  H, (float)S*H);
    C2 b2=crot<S>(s2);
    C2 b3=cmulc(s3, -H, (float)S*H);
    C2 c0=cadd(a0,a2), c1=cadd(a1,a3), d0=csub(a0,a2), d1=crot<S>(csub(a1,a3));
    C2 e0=cadd(b0,b2), e1=cadd(b1,b3), f0=csub(b0,b2), f1=crot<S>(csub(b1,b3));
    r[0]=cadd(c0,c1); r[4]=csub(c0,c1);
    r[2]=cadd(d0,d1); r[6]=csub(d0,d1);
    r[1]=cadd(e0,e1); r[5]=csub(e0,e1);
    r[3]=cadd(f0,f1); r[7]=csub(f0,f1);
}

// per-thread twiddles: tw[d-1] = exp(+i*2*pi*t*d/64), d=1..7
__device__ __forceinline__ void make_tw(C2 tw[7], int t) {
    float ang = (6.28318530717958647692f/64.f) * (float)t;
    float s, c; __sincosf(ang, &s, &c);
    tw[0] = C2{c, s};
#pragma unroll
    for (int d=1; d<7; d++)
        tw[d] = C2{tw[d-1].re*c - tw[d-1].im*s, tw[d-1].re*s + tw[d-1].im*c};
}

template<int S>
__device__ __forceinline__ void apply_tw(C2 r[8], const C2 tw[7]) {
#pragma unroll
    for (int d=1;d<8;d++){
        float cs = tw[d-1].re;
        float sn = (S == -1) ? -tw[d-1].im : tw[d-1].im;
        r[d] = cmulc(r[d], cs, sn);
    }
}

// 64-pt FFT, row-local (the 8 cooperating threads are consecutive in one warp).
// Sg = this row's 64-cell float2 scratch; pxor = (row&1)<<3 (bank-parity split).
template<int S>
__device__ __forceinline__ void fft64w(C2 r[8], float2* Sg, int t, int pxor, const C2 tw[7]) {
    fft8<S>(r);
    apply_tw<S>(r, tw);
    __syncwarp();
#pragma unroll
    for (int d=0;d<8;d++){ int p = (8*d + ((d+t)&7)) ^ pxor; Sg[p] = make_float2(r[d].re, r[d].im); }
    __syncwarp();
#pragma unroll
    for (int b=0;b<8;b++){ int p = (8*t + ((b+t)&7)) ^ pxor; float2 v = Sg[p]; r[b] = C2{v.x, v.y}; }
    __syncwarp();
    fft8<S>(r);
}

// 64-pt FFT, cross-warp (thread octet q, line id kz; 8 cooperating threads are
// tid = kz + 64*q). Transpose via T[p][kz] (64x64 float2 plane). Leading
// __syncthreads protects T against prior readers.
template<int S>
__device__ __forceinline__ void fft64x(C2 r[8], float2* T, int kz, int q, const C2 tw[7]) {
    fft8<S>(r);
    apply_tw<S>(r, tw);
    __syncthreads();
#pragma unroll
    for (int d=0;d<8;d++){ int p = 8*d + ((d+q)&7); T[p*64 + kz] = make_float2(r[d].re, r[d].im); }
    __syncthreads();
#pragma unroll
    for (int b=0;b<8;b++){ int p = 8*q + ((b+q)&7); float2 v = T[p*64 + kz]; r[b] = C2{v.x, v.y}; }
    fft8<S>(r);
}

// plane cell index with bank-parity xor (consistent store/load bijection)
__device__ __forceinline__ int pcidx(int row, int col) {
    return row*64 + (col ^ ((row&1)<<3));
}

__device__ __forceinline__ void corner(float u, int hi, int& i0, int& i1, float& d) {
    float f = floorf(u);
    int ii = (int)f;
    i0 = min(max(ii, 0), hi);
    i1 = min(max(ii + 1, 0), hi);
    d = u - (float)i0;          // delta vs *clipped* lower corner (matches reference)
}

// z-axis corner for pair-fetch arrays: i0 clamped; d forced to 0 on low-side
// degeneracy (floor(u) < 0 => reference has z0==z1, dz-weights cancel exactly).
// High side handled by the self-pair stored at index hi.
__device__ __forceinline__ void cornerz(float u, int hi, int& i0, float& d) {
    float f = floorf(u);
    int ii = (int)f;
    i0 = min(max(ii, 0), hi);
    d = (f < 0.f) ? 0.f : (u - (float)i0);
}

// per-thread affine params from theta (cheap; every thread redundantly)
__device__ __forceinline__ void make_mat(const float* __restrict__ theta, int b,
                                         float R[9], float C[3]) {
    float t0=theta[b*6+0], t1=theta[b*6+1], t2=theta[b*6+2];
    float t3=theta[b*6+3], t4=theta[b*6+4], t5=theta[b*6+5];
    float phi = t0*2.f*PI_F - PI_F;
    float th  = t1*2.f*PI_F - PI_F;
    float psi = t2*2.f*PI_F - PI_F;
    float cf=cosf(phi), sf=sinf(phi), ct=cosf(th), st=sinf(th), cp=cosf(psi), sp=sinf(psi);
    R[0] =  cf*ct*cp - sf*sp;
    R[1] =  sf*ct*cp + cf*sp;
    R[2] = -st*cp;
    R[3] = -cf*ct*sp - sf*cp;
    R[4] = -sf*ct*sp + cf*cp;
    R[5] =  st*sp;
    R[6] =  cf*st;
    R[7] =  sf*st;
    R[8] =  ct;
    const float s = 64.f/66.f;
    float l0 = (2.f*t3-1.f)*s, l1=(2.f*t4-1.f)*s, l2=(2.f*t5-1.f)*s;
    C[0] = -(R[0]*l0 + R[1]*l1 + R[2]*l2);
    C[1] = -(R[3]*l0 + R[4]*l1 + R[5]*l2);
    C[2] = -(R[6]*l0 + R[7]*l1 + R[8]*l2);
}

// ---------------- prepack kernel: z-pair interleave (m1,m2) -> g_m12p ----------------
__global__ void pack_masks_kernel(const float* __restrict__ m1,
                                  const float* __restrict__ m2) {
    int v = blockIdx.x*256 + threadIdx.x;         // voxel index over BN*VOX
    int z = v & 63;
    int vn = v + (z < 63 ? 1 : 0);                // z-neighbor (self-pair at z=63)
    g_m12p[v] = make_float4(m1[v], m2[v], m1[vn], m2[vn]);
}

// ---------------- merged kernel A: mask warp (this plane) + X warp + pack + fwd z,y FFT ----------------
// Block = one (b,x) plane. Phase 0: warp (m1,m2) for plane i=x via z-pair quads
// (4 LDG.128 per voxel). Phase 1: inline X gather + W = X_t + i*Y, forward FFT z,y -> g_fw.
__global__ void __launch_bounds__(512, 2) fftA_kernel(const float* __restrict__ X,
                                                      const float* __restrict__ Y,
                                                      const float* __restrict__ theta,
                                                      float* __restrict__ o1,
                                                      float* __restrict__ o2) {
    extern __shared__ float2 s[];          // 4096 float2
    int bx = blockIdx.x;                  // b*64 + x
    int b = bx >> 6, x = bx & 63;
    int tid = threadIdx.x;

    float R[9], C[3];
    make_mat(theta, b, R, C);
    int base = b << 18;

    // ---- phase 0: mask warp for output plane i = x (rotation only, 64-grid, clamp) ----
    {
        const float4* p12 = g_m12p + base;
        float gx = -1.f + (float)x*(2.f/63.f);
        float bxm = R[0]*gx, bym = R[3]*gx, bzm = R[6]*gx;
        for (int ii=0; ii<8; ii++){
            int idx = tid + ii*512;
            int j = idx>>6, k = idx&63;
            float gy = -1.f + (float)j*(2.f/63.f);
            float gz = -1.f + (float)k*(2.f/63.f);
            float sx = bxm + R[1]*gy + R[2]*gz;
            float sy = bym + R[4]*gy + R[5]*gz;
            float sz = bzm + R[7]*gy + R[8]*gz;
            float ux = (sx+1.f)*31.5f, uy=(sy+1.f)*31.5f, uz=(sz+1.f)*31.5f;
            int x0,x1,y0,y1; float dx,dy;
            corner(ux,63,x0,x1,dx); corner(uy,63,y0,y1,dy);
            int z0; float dz; cornerz(uz,63,z0,dz);
            float wx0=1.f-dx, wy0=1.f-dy, wz0=1.f-dz;
            float4 q00 = p12[(x0<<12)+(y0<<6)+z0];
            float4 q01 = p12[(x0<<12)+(y1<<6)+z0];
            float4 q10 = p12[(x1<<12)+(y0<<6)+z0];
            float4 q11 = p12[(x1<<12)+(y1<<6)+z0];
            // z-lerp per (x,y) corner, then y, then x
            float a1 = q00.x*wz0 + q00.z*dz, a2 = q00.y*wz0 + q00.w*dz;
            float b1 = q01.x*wz0 + q01.z*dz, b2 = q01.y*wz0 + q01.w*dz;
            float c1 = q10.x*wz0 + q10.z*dz, c2 = q10.y*wz0 + q10.w*dz;
            float d1 = q11.x*wz0 + q11.z*dz, d2 = q11.y*wz0 + q11.w*dz;
            float v1 = wx0*(wy0*a1 + dy*b1) + dx*(wy0*c1 + dy*d1);
            float v2 = wx0*(wy0*a2 + dy*b2) + dx*(wy0*c2 + dy*d2);
            int oidx = base + (x<<12) + idx;
            o1[oidx] = v1;
            o2[oidx] = v2;
        }
    }

    // ---- phase 1: X warp + pack + forward FFT ----
    int g = tid>>3, t = tid&7;            // pass-1: row y=g, octet t (same warp)
    const float* Xb = X + ((size_t)b << 18);
    const float* Yb = Y + ((size_t)bx << 12);

    // padded-66 grid coords for this (x, y=g) line; z = 8a+t
    float gxc = -1.f + (float)(x+1)*(2.f/65.f);
    float gyc = -1.f + (float)(g+1)*(2.f/65.f);
    float bxs = R[0]*gxc + R[1]*gyc + C[0];
    float bys = R[3]*gxc + R[4]*gyc + C[1];
    float bzs = R[6]*gxc + R[7]*gyc + C[2];

    C2 r[8];
#pragma unroll
    for (int a=0;a<8;a++){
        int z = 8*a + t;
        float gzc = -1.f + (float)(z+1)*(2.f/65.f);
        float sx = bxs + R[2]*gzc;
        float sy = bys + R[5]*gzc;
        float sz = bzs + R[8]*gzc;
        float ux=(sx+1.f)*32.5f, uy=(sy+1.f)*32.5f, uz=(sz+1.f)*32.5f;
        int x0,x1,y0,y1,z0,z1; float dx,dy,dz;
        corner(ux,65,x0,x1,dx); corner(uy,65,y0,y1,dy); corner(uz,65,z0,z1,dz);
        float wx0=1.f-dx, wy0=1.f-dy, wz0=1.f-dz;
        auto fetch = [&](int p,int q,int rr)->float{
            if ((unsigned)(p-1)<64u && (unsigned)(q-1)<64u && (unsigned)(rr-1)<64u)
                return Xb[((p-1)<<12) + ((q-1)<<6) + (rr-1)];
            return 0.f;
        };
        float v = wx0*wy0*wz0*fetch(x0,y0,z0) + wx0*wy0*dz*fetch(x0,y0,z1)
                + wx0*dy*wz0*fetch(x0,y1,z0)  + wx0*dy*dz*fetch(x0,y1,z1)
                + dx*wy0*wz0*fetch(x1,y0,z0)  + dx*wy0*dz*fetch(x1,y0,z1)
                + dx*dy*wz0*fetch(x1,y1,z0)   + dx*dy*dz*fetch(x1,y1,z1);
        float yv = Yb[(g<<6) + z];
        r[a] = C2{v, yv};                 // W = X_t + i*Y
    }

    C2 tw[7]; make_tw(tw, t);
    fft64w<-1>(r, s + g*64, t, (g&1)<<3, tw);     // forward z (row-local)
#pragma unroll
    for (int c=0;c<8;c++) s[pcidx(g, 8*c+t)] = make_float2(r[c].re, r[c].im);
    __syncthreads();

    // pass 2: forward y. remap: q = octet, kz = line id
    int q = tid>>6, kz = tid&63;
#pragma unroll
    for (int a=0;a<8;a++){ float2 v = s[pcidx(8*a+q, kz)]; r[a] = C2{v.x, v.y}; }
    C2 tw2[7]; make_tw(tw2, q);
    fft64x<-1>(r, s, kz, q, tw2);

    float2* dst = g_fw + ((size_t)bx << 12);
#pragma unroll
    for (int c=0;c<8;c++) dst[(8*c+q)*64 + kz] = make_float2(r[c].re, r[c].im);
}

// ---------------- FFT kernel B: fwd-x, pointwise Z*E (symmetrized masks), inv-x ----------------
// Fully register-resident: coalesced direct loads/stores; smem only for transposes.
// E[k] = 0.5*((w1[k]+w1[-k]) - i*(w2[k]+w2[-k])), w_i[k] = M_i_t[(k+32) mod 64 per axis]
__global__ void __launch_bounds__(512, 2) fftB_kernel(const float* __restrict__ m1t,
                                                      const float* __restrict__ m2t) {
    extern __shared__ float2 s[];          // 4096 float2 transpose plane
    int bid = blockIdx.x;                 // b*64 + ky
    int b = bid >> 6, y = bid & 63;
    int tid = threadIdx.x;
    int q = tid>>6, kz = tid&63;          // line kz along x, octet q

    size_t base = ((size_t)b << 18);
    size_t ybase = base + ((size_t)y << 6);
    int ys  = y ^ 32;
    int ys2 = (32 - y) & 63;

    // spectrum: direct coalesced loads in consumption order
    C2 r[8];
#pragma unroll
    for (int a=0;a<8;a++){
        float2 v = g_fw[ybase + ((size_t)(8*a+q)<<12) + kz];
        r[a] = C2{v.x, v.y};
    }
    // masks: direct coalesced loads; combine to E in regs
    float er[8], ei[8];
    {
        int zs  = kz ^ 32;
        int zs2 = (32 - kz) & 63;
#pragma unroll
        for (int c=0;c<8;c++){
            int kx  = 8*c + q;
            int xs  = kx ^ 32;
            int xs2 = (32 - kx) & 63;
            size_t o1 = base + ((size_t)xs <<12) + (ys <<6) + zs;
            size_t o2 = base + ((size_t)xs2<<12) + (ys2<<6) + zs2;
            er[c] =  0.5f*(m1t[o1] + m1t[o2]);
            ei[c] = -0.5f*(m2t[o1] + m2t[o2]);
        }
    }

    C2 tw[7]; make_tw(tw, q);
    fft64x<-1>(r, s, kz, q, tw);          // forward x
#pragma unroll
    for (int c=0;c<8;c++) r[c] = cmulc(r[c], er[c], ei[c]);
    fft64x<1>(r, s, kz, q, tw);           // inverse x

#pragma unroll
    for (int c=0;c<8;c++)
        g_fw[ybase + ((size_t)(8*c+q)<<12) + kz] = make_float2(r[c].re, r[c].im);
}

// ---------------- FFT kernel C: inverse z then y, scale, real part ----------------
__global__ void __launch_bounds__(512, 2) fftC_kernel(float* __restrict__ out0) {
    extern __shared__ float2 s[];          // 4096 float2
    int bx = blockIdx.x;
    int tid = threadIdx.x;
    int g = tid>>3, t = tid&7;

    const float2* src = g_fw + ((size_t)bx << 12);
    C2 r[8];
#pragma unroll
    for (int a=0;a<8;a++){
        float2 v = src[(g<<6) + 8*a + t];
        r[a] = C2{v.x, v.y};
    }
    C2 tw[7]; make_tw(tw, t);
    fft64w<1>(r, s + g*64, t, (g&1)<<3, tw);      // inverse z (row-local)
#pragma unroll
    for (int c=0;c<8;c++) s[pcidx(g, 8*c+t)] = make_float2(r[c].re, r[c].im);
    __syncthreads();

    // pass 2: inverse y
    int q = tid>>6, kz = tid&63;
#pragma unroll
    for (int a=0;a<8;a++){ float2 v = s[pcidx(8*a+q, kz)]; r[a] = C2{v.x, v.y}; }
    C2 tw2[7]; make_tw(tw2, q);
    fft64x<1>(r, s, kz, q, tw2);

    const float sc = 1.f/262144.f;   // 1/64^3
    float* dst = out0 + ((size_t)bx << 12);
#pragma unroll
    for (int c=0;c<8;c++) dst[(8*c+q)*64 + kz] = r[c].re * sc;
}

// ---------------- launcher ----------------
extern "C" void kernel_launch(void* const* d_in, const int* in_sizes, int n_in,
                              void* d_out, int out_size) {
    const float* X  = (const float*)d_in[0];
    const float* Y  = (const float*)d_in[1];
    const float* m1 = (const float*)d_in[2];
    const float* m2 = (const float*)d_in[3];
    const float* th = (const float*)d_in[4];
    float* out0 = (float*)d_out;                 // real(ifft(...))
    float* out1 = out0 + (size_t)BN*VOX;         // M1_t
    float* out2 = out1 + (size_t)BN*VOX;         // M2_t

    const int SM = 4096 * 8;   // 32,768 B: one 64x64 float2 plane

    pack_masks_kernel<<<(BN*VOX)/256, 256>>>(m1, m2);
    fftA_kernel<<<BN*NN, 512, SM>>>(X, Y, th, out1, out2);   // masks + X warp + fwd FFT
    fftB_kernel<<<BN*NN, 512, SM>>>(out1, out2);             // x FFT + Z*E + x IFFT
    fftC_kernel<<<BN*NN, 512, SM>>>(out0);                   // z,y IFFT + real
}